// round 3
// baseline (speedup 1.0000x reference)
#include <cuda_runtime.h>
#include <math.h>

#define TT 384
#define CC 512
#define HH 8
#define DD 64
#define EE 16

// ---------------- scratch (device globals; no allocs allowed) ----------------
__device__ float g_h  [TT*CC];        // LN1 output
__device__ float g_qkv[TT*3*CC];      // QKV
__device__ float g_EK [EE*CC];        // edge-k table
__device__ float g_EV [EE*CC];        // edge-v table
__device__ float g_y  [TT*CC];        // attention output (pre-proj)
__device__ float g_x1 [TT*CC];        // x + attn
__device__ float g_h2 [TT*CC];        // LN2 output
__device__ float g_fc [TT*4*CC];      // GELU(fc)

// ---------------- edge table precompute: EK/EV = edge_emb @ W^T + b ----------
__global__ void edge_pre(const float* __restrict__ emb,
                         const float* __restrict__ Wk, const float* __restrict__ bk,
                         const float* __restrict__ Wv, const float* __restrict__ bv,
                         float* __restrict__ EK, float* __restrict__ EV) {
    int e = blockIdx.x;           // 16 blocks
    int n = threadIdx.x;          // 512 threads
    __shared__ float er[CC];
    er[n] = emb[e*CC + n];
    __syncthreads();
    const float4* wk = (const float4*)(Wk + n*CC);
    const float4* wv = (const float4*)(Wv + n*CC);
    float sk = 0.f, sv = 0.f;
    #pragma unroll 4
    for (int k = 0; k < CC/4; k++) {
        float4 a = wk[k], b = wv[k];
        float e0 = er[4*k+0], e1 = er[4*k+1], e2 = er[4*k+2], e3 = er[4*k+3];
        sk = fmaf(e0,a.x, fmaf(e1,a.y, fmaf(e2,a.z, fmaf(e3,a.w, sk))));
        sv = fmaf(e0,b.x, fmaf(e1,b.y, fmaf(e2,b.z, fmaf(e3,b.w, sv))));
    }
    EK[e*CC + n] = sk + bk[n];
    EV[e*CC + n] = sv + bv[n];
}

// ---------------- layernorm (row of 512, 256 threads/row) -------------------
__global__ void ln_kernel(const float* __restrict__ x, const float* __restrict__ w,
                          const float* __restrict__ b, float* __restrict__ out) {
    int row = blockIdx.x;
    int tid = threadIdx.x;                 // 256
    int lane = tid & 31, wid = tid >> 5;
    const float* xr = x + row*CC;
    float v0 = xr[tid], v1 = xr[tid + 256];

    __shared__ float rbuf[8];
    __shared__ float stats[2];

    float s = v0 + v1;
    #pragma unroll
    for (int o = 16; o > 0; o >>= 1) s += __shfl_xor_sync(0xffffffffu, s, o);
    if (lane == 0) rbuf[wid] = s;
    __syncthreads();
    if (tid == 0) {
        float t = 0.f;
        #pragma unroll
        for (int i = 0; i < 8; i++) t += rbuf[i];
        stats[0] = t * (1.0f/CC);
    }
    __syncthreads();
    float mu = stats[0];
    float d0 = v0 - mu, d1 = v1 - mu;
    float q = d0*d0 + d1*d1;
    #pragma unroll
    for (int o = 16; o > 0; o >>= 1) q += __shfl_xor_sync(0xffffffffu, q, o);
    if (lane == 0) rbuf[wid] = q;
    __syncthreads();
    if (tid == 0) {
        float t = 0.f;
        #pragma unroll
        for (int i = 0; i < 8; i++) t += rbuf[i];
        stats[1] = rsqrtf(t * (1.0f/CC) + 1e-5f);
    }
    __syncthreads();
    float rstd = stats[1];
    out[row*CC + tid]       = d0 * rstd * w[tid]       + b[tid];
    out[row*CC + tid + 256] = d1 * rstd * w[tid + 256] + b[tid + 256];
}

// ---------------- generic NT GEMM: C[m,n] = sum_k A[m,k]*B[n,k] + bias[n] ----
// EPI: 0 = bias only, 1 = bias + residual, 2 = bias + exact GELU
// BM=BN=64, BK=16, 256 threads, 4x4 register microtile. All dims divide tiles.
template<int EPI>
__global__ void gemm_nt(const float* __restrict__ A, const float* __restrict__ B,
                        const float* __restrict__ bias, const float* __restrict__ res,
                        float* __restrict__ Cout, int M, int N, int K) {
    __shared__ float As[16][68];
    __shared__ float Bs[16][68];
    int tid = threadIdx.x;
    int bm = blockIdx.y * 64, bn = blockIdx.x * 64;
    int tx = tid & 15, ty = tid >> 4;
    int lr = tid >> 2;            // 0..63
    int lc = (tid & 3) << 2;      // 0,4,8,12

    const float* Ap = A + (size_t)(bm + lr)*K + lc;
    const float* Bp = B + (size_t)(bn + lr)*K + lc;

    float acc[4][4] = {};
    for (int k0 = 0; k0 < K; k0 += 16) {
        float4 a = *(const float4*)(Ap + k0);
        float4 b = *(const float4*)(Bp + k0);
        As[lc+0][lr] = a.x; As[lc+1][lr] = a.y; As[lc+2][lr] = a.z; As[lc+3][lr] = a.w;
        Bs[lc+0][lr] = b.x; Bs[lc+1][lr] = b.y; Bs[lc+2][lr] = b.z; Bs[lc+3][lr] = b.w;
        __syncthreads();
        #pragma unroll
        for (int k = 0; k < 16; k++) {
            float ar[4], br[4];
            #pragma unroll
            for (int u = 0; u < 4; u++) { ar[u] = As[k][ty*4+u]; br[u] = Bs[k][tx*4+u]; }
            #pragma unroll
            for (int mi = 0; mi < 4; mi++)
                #pragma unroll
                for (int ni = 0; ni < 4; ni++)
                    acc[mi][ni] = fmaf(ar[mi], br[ni], acc[mi][ni]);
        }
        __syncthreads();
    }
    #pragma unroll
    for (int mi = 0; mi < 4; mi++) {
        int m = bm + ty*4 + mi;
        #pragma unroll
        for (int ni = 0; ni < 4; ni++) {
            int n = bn + tx*4 + ni;
            float v = acc[mi][ni] + bias[n];
            if (EPI == 1) v += res[(size_t)m*N + n];
            if (EPI == 2) v = 0.5f * v * (1.0f + erff(v * 0.70710678118654752f));
            Cout[(size_t)m*N + n] = v;
        }
    }
}

// ---------------- gather attention: block per (i, h), 128 threads ------------
// scores[j] = (sum_d q[i,h,d]*k[j,h,d]*EK[e_ij,h,d]) / 8 + ab[e_ij,h],  j <= i
// y[i,h,d]  = sum_j softmax(scores)[j] * v[j,h,d] * EV[e_ij,h,d]
__global__ void attn_kernel(const float* __restrict__ qkv, const int* __restrict__ bm,
                            const float* __restrict__ EK, const float* __restrict__ EV,
                            const float* __restrict__ abe, float* __restrict__ y) {
    int i = blockIdx.x, h = blockIdx.y;
    int tid = threadIdx.x;                // 128
    int lane = tid & 31, wid = tid >> 5;

    __shared__ float q_s[DD];
    __shared__ float EK_s[EE*DD];
    __shared__ float EV_s[EE*DD];
    __shared__ float ab_s[EE];
    __shared__ float s_s[TT];
    __shared__ int   e_s[TT];
    __shared__ float psum[2][DD];
    __shared__ float rbuf[4];
    __shared__ float resv[2];

    if (tid < DD) q_s[tid] = qkv[i*3*CC + h*DD + tid];
    for (int idx = tid; idx < EE*DD; idx += 128) {
        int e = idx / DD, d = idx % DD;
        EK_s[idx] = EK[e*CC + h*DD + d];
        EV_s[idx] = EV[e*CC + h*DD + d];
    }
    if (tid < EE) ab_s[tid] = abe[tid*HH + h];
    __syncthreads();

    // pass 1: raw scores, one warp per j (strided by 4 warps)
    for (int j = wid; j <= i; j += 4) {
        int e = bm[i*TT + j];
        const float* kr = qkv + j*3*CC + CC + h*DD;
        float s = q_s[lane]      * kr[lane]      * EK_s[e*DD + lane]
                + q_s[lane + 32] * kr[lane + 32] * EK_s[e*DD + lane + 32];
        #pragma unroll
        for (int o = 16; o > 0; o >>= 1) s += __shfl_xor_sync(0xffffffffu, s, o);
        if (lane == 0) { s_s[j] = s * 0.125f + ab_s[e]; e_s[j] = e; }
    }
    __syncthreads();

    // block max over j in [0, i]
    float lm = -1e30f;
    for (int j = tid; j <= i; j += 128) lm = fmaxf(lm, s_s[j]);
    #pragma unroll
    for (int o = 16; o > 0; o >>= 1) lm = fmaxf(lm, __shfl_xor_sync(0xffffffffu, lm, o));
    if (lane == 0) rbuf[wid] = lm;
    __syncthreads();
    if (tid == 0) resv[0] = fmaxf(fmaxf(rbuf[0], rbuf[1]), fmaxf(rbuf[2], rbuf[3]));
    __syncthreads();
    float m = resv[0];

    // exp + sum
    float ls = 0.f;
    for (int j = tid; j <= i; j += 128) {
        float p = __expf(s_s[j] - m);
        s_s[j] = p;
        ls += p;
    }
    #pragma unroll
    for (int o = 16; o > 0; o >>= 1) ls += __shfl_xor_sync(0xffffffffu, ls, o);
    if (lane == 0) rbuf[wid] = ls;
    __syncthreads();
    if (tid == 0) resv[1] = 1.0f / (rbuf[0] + rbuf[1] + rbuf[2] + rbuf[3]);
    __syncthreads();
    float inv = resv[1];

    // pass 2: weighted V accumulate; threads split into 2 j-halves x 64 d
    int d = tid & 63, half = tid >> 6;
    float acc = 0.f;
    for (int j = half; j <= i; j += 2) {
        int e = e_s[j];
        acc = fmaf(s_s[j], qkv[j*3*CC + 2*CC + h*DD + d] * EV_s[e*DD + d], acc);
    }
    psum[half][d] = acc;
    __syncthreads();
    if (tid < DD) y[i*CC + h*DD + tid] = (psum[0][tid] + psum[1][tid]) * inv;
}

// ---------------- host launch ------------------------------------------------
extern "C" void kernel_launch(void* const* d_in, const int* in_sizes, int n_in,
                              void* d_out, int out_size) {
    const float* x        = (const float*)d_in[0];
    const int*   bmx      = (const int*)  d_in[1];
    const float* ln1_w    = (const float*)d_in[2];
    const float* ln1_b    = (const float*)d_in[3];
    const float* w_attn_w = (const float*)d_in[4];
    const float* w_attn_b = (const float*)d_in[5];
    const float* w_proj_w = (const float*)d_in[6];
    const float* w_proj_b = (const float*)d_in[7];
    const float* abe      = (const float*)d_in[8];
    const float* edge_emb = (const float*)d_in[9];
    const float* wek      = (const float*)d_in[10];
    const float* bek      = (const float*)d_in[11];
    const float* wev      = (const float*)d_in[12];
    const float* bev      = (const float*)d_in[13];
    const float* ln2_w    = (const float*)d_in[14];
    const float* ln2_b    = (const float*)d_in[15];
    const float* c_fc_w   = (const float*)d_in[16];
    const float* c_fc_b   = (const float*)d_in[17];
    const float* c_proj_w = (const float*)d_in[18];
    const float* c_proj_b = (const float*)d_in[19];
    float* out = (float*)d_out;

    float *pH, *pQKV, *pEK, *pEV, *pY, *pX1, *pH2, *pFC;
    cudaGetSymbolAddress((void**)&pH,   g_h);
    cudaGetSymbolAddress((void**)&pQKV, g_qkv);
    cudaGetSymbolAddress((void**)&pEK,  g_EK);
    cudaGetSymbolAddress((void**)&pEV,  g_EV);
    cudaGetSymbolAddress((void**)&pY,   g_y);
    cudaGetSymbolAddress((void**)&pX1,  g_x1);
    cudaGetSymbolAddress((void**)&pH2,  g_h2);
    cudaGetSymbolAddress((void**)&pFC,  g_fc);

    // 1. edge tables (16x512 each)
    edge_pre<<<EE, CC>>>(edge_emb, wek, bek, wev, bev, pEK, pEV);
    // 2. LN1
    ln_kernel<<<TT, 256>>>(x, ln1_w, ln1_b, pH);
    // 3. QKV = LN1 @ w_attn^T + b   (384 x 1536 x 512)
    gemm_nt<0><<<dim3(3*CC/64, TT/64), 256>>>(pH, w_attn_w, w_attn_b, nullptr, pQKV, TT, 3*CC, CC);
    // 4. gather attention
    attn_kernel<<<dim3(TT, HH), 128>>>(pQKV, bmx, pEK, pEV, abe, pY);
    // 5. x1 = x + y @ w_proj^T + b  (384 x 512 x 512)
    gemm_nt<1><<<dim3(CC/64, TT/64), 256>>>(pY, w_proj_w, w_proj_b, x, pX1, TT, CC, CC);
    // 6. LN2
    ln_kernel<<<TT, 256>>>(pX1, ln2_w, ln2_b, pH2);
    // 7. fc = gelu(h2 @ c_fc^T + b) (384 x 2048 x 512)
    gemm_nt<2><<<dim3(4*CC/64, TT/64), 256>>>(pH2, c_fc_w, c_fc_b, nullptr, pFC, TT, 4*CC, CC);
    // 8. out = x1 + fc @ c_proj^T + b (384 x 512 x 2048)
    gemm_nt<1><<<dim3(CC/64, TT/64), 256>>>(pFC, c_proj_w, c_proj_b, pX1, out, TT, CC, 4*CC);
}

// round 4
// speedup vs baseline: 1.3851x; 1.3851x over previous
#include <cuda_runtime.h>
#include <math.h>
#include <stdint.h>

#define TT 384
#define CC 512
#define HH 8
#define DD 64
#define EE 16

// ---------------- scratch (device globals; no allocs allowed) ----------------
__device__ float g_h  [TT*CC];        // LN1 output
__device__ float g_qkv[TT*3*CC];      // QKV
__device__ float g_EK [EE*CC];        // edge-k table (unused by attn now, kept for clarity)
__device__ float g_EV [EE*CC];        // edge-v table
__device__ float g_EKt[CC*EE];        // edge-k table transposed: [c][e]
__device__ float g_Kt [CC*TT];        // K transposed: [c][j]
__device__ float g_y  [TT*CC];        // attention output (pre-proj)
__device__ float g_x1 [TT*CC];        // x + attn
__device__ float g_h2 [TT*CC];        // LN2 output
__device__ float g_fc [TT*4*CC];      // GELU(fc)

// ---------------- edge table precompute: EK/EV = edge_emb @ W^T + b ----------
__global__ void edge_pre(const float* __restrict__ emb,
                         const float* __restrict__ Wk, const float* __restrict__ bk,
                         const float* __restrict__ Wv, const float* __restrict__ bv,
                         float* __restrict__ EK, float* __restrict__ EKt,
                         float* __restrict__ EV) {
    int e = blockIdx.x;           // 16 blocks
    int n = threadIdx.x;          // 512 threads
    __shared__ float er[CC];
    er[n] = emb[e*CC + n];
    __syncthreads();
    const float4* wk = (const float4*)(Wk + n*CC);
    const float4* wv = (const float4*)(Wv + n*CC);
    float sk = 0.f, sv = 0.f;
    #pragma unroll 4
    for (int k = 0; k < CC/4; k++) {
        float4 a = wk[k], b = wv[k];
        float e0 = er[4*k+0], e1 = er[4*k+1], e2 = er[4*k+2], e3 = er[4*k+3];
        sk = fmaf(e0,a.x, fmaf(e1,a.y, fmaf(e2,a.z, fmaf(e3,a.w, sk))));
        sv = fmaf(e0,b.x, fmaf(e1,b.y, fmaf(e2,b.z, fmaf(e3,b.w, sv))));
    }
    float rk = sk + bk[n];
    EK [e*CC + n] = rk;
    EKt[n*EE + e] = rk;
    EV [e*CC + n] = sv + bv[n];
}

// ---------------- K transpose: Kt[c][j] = qkv[j][CC + c] ---------------------
__global__ void transpose_k(const float* __restrict__ qkv, float* __restrict__ Kt) {
    __shared__ float t[32][33];
    int c0 = blockIdx.x * 32, j0 = blockIdx.y * 32;
    int tx = threadIdx.x, ty = threadIdx.y;        // (32, 8)
    #pragma unroll
    for (int r = 0; r < 32; r += 8)
        t[ty + r][tx] = qkv[(size_t)(j0 + ty + r)*3*CC + CC + c0 + tx];
    __syncthreads();
    #pragma unroll
    for (int r = 0; r < 32; r += 8)
        Kt[(size_t)(c0 + ty + r)*TT + j0 + tx] = t[tx][ty + r];
}

// ---------------- layernorm (row of 512, 256 threads/row) -------------------
__global__ void ln_kernel(const float* __restrict__ x, const float* __restrict__ w,
                          const float* __restrict__ b, float* __restrict__ out) {
    int row = blockIdx.x;
    int tid = threadIdx.x;                 // 256
    int lane = tid & 31, wid = tid >> 5;
    const float* xr = x + row*CC;
    float v0 = xr[tid], v1 = xr[tid + 256];

    __shared__ float rbuf[8];
    __shared__ float stats[2];

    float s = v0 + v1;
    #pragma unroll
    for (int o = 16; o > 0; o >>= 1) s += __shfl_xor_sync(0xffffffffu, s, o);
    if (lane == 0) rbuf[wid] = s;
    __syncthreads();
    if (tid == 0) {
        float t = 0.f;
        #pragma unroll
        for (int i = 0; i < 8; i++) t += rbuf[i];
        stats[0] = t * (1.0f/CC);
    }
    __syncthreads();
    float mu = stats[0];
    float d0 = v0 - mu, d1 = v1 - mu;
    float q = d0*d0 + d1*d1;
    #pragma unroll
    for (int o = 16; o > 0; o >>= 1) q += __shfl_xor_sync(0xffffffffu, q, o);
    if (lane == 0) rbuf[wid] = q;
    __syncthreads();
    if (tid == 0) {
        float t = 0.f;
        #pragma unroll
        for (int i = 0; i < 8; i++) t += rbuf[i];
        stats[1] = rsqrtf(t * (1.0f/CC) + 1e-5f);
    }
    __syncthreads();
    float rstd = stats[1];
    out[row*CC + tid]       = d0 * rstd * w[tid]       + b[tid];
    out[row*CC + tid + 256] = d1 * rstd * w[tid + 256] + b[tid + 256];
}

// ---------------- tf32 tensor-core NT GEMM ----------------------------------
// C[m,n] = sum_k A[m,k]*B[n,k] + bias[n] ; EPI: 0=bias, 1=bias+res, 2=bias+GELU
// BM=BN=64, BK=32, 128 threads (4 warps in 2x2), warp tile 32x32 (2x4 mma m16n8k8)
__device__ __forceinline__ void mma_tf32(float c[4], const uint32_t a[4], const uint32_t b[2]) {
    asm volatile(
        "mma.sync.aligned.m16n8k8.row.col.f32.tf32.tf32.f32 "
        "{%0,%1,%2,%3}, {%4,%5,%6,%7}, {%8,%9}, {%0,%1,%2,%3};\n"
        : "+f"(c[0]), "+f"(c[1]), "+f"(c[2]), "+f"(c[3])
        : "r"(a[0]), "r"(a[1]), "r"(a[2]), "r"(a[3]), "r"(b[0]), "r"(b[1]));
}
__device__ __forceinline__ uint32_t f2tf32(float x) {
    uint32_t r;
    asm("cvt.rna.tf32.f32 %0, %1;\n" : "=r"(r) : "f"(x));
    return r;
}
__device__ __forceinline__ float epi_apply(float v, float r, int EPI) {
    if (EPI == 1) v += r;
    if (EPI == 2) v = 0.5f * v * (1.0f + erff(v * 0.70710678118654752f));
    return v;
}

template<int EPI>
__global__ void gemm_tc(const float* __restrict__ A, const float* __restrict__ B,
                        const float* __restrict__ bias, const float* __restrict__ res,
                        float* __restrict__ Cout, int M, int N, int K) {
    __shared__ uint32_t As[64][36];
    __shared__ uint32_t Bs[64][36];
    int tid = threadIdx.x;            // 128
    int warp = tid >> 5, lane = tid & 31;
    int wm = warp & 1, wn = warp >> 1;        // 2 x 2 warps
    int bm = blockIdx.y * 64, bn = blockIdx.x * 64;
    int lr = tid >> 3;                // 0..15 (row within 16-row slab)
    int lc = tid & 7;                 // 0..7  (float4 column)

    const float* Ap = A + (size_t)(bm + lr)*K + lc*4;
    const float* Bp = B + (size_t)(bn + lr)*K + lc*4;

    float acc[2][4][4] = {};

    for (int k0 = 0; k0 < K; k0 += 32) {
        #pragma unroll
        for (int rr = 0; rr < 4; rr++) {
            float4 a = *(const float4*)(Ap + (size_t)(rr*16)*K + k0);
            float4 b = *(const float4*)(Bp + (size_t)(rr*16)*K + k0);
            uint4 at = make_uint4(f2tf32(a.x), f2tf32(a.y), f2tf32(a.z), f2tf32(a.w));
            uint4 bt = make_uint4(f2tf32(b.x), f2tf32(b.y), f2tf32(b.z), f2tf32(b.w));
            *(uint4*)&As[lr + 16*rr][lc*4] = at;
            *(uint4*)&Bs[lr + 16*rr][lc*4] = bt;
        }
        __syncthreads();
        #pragma unroll
        for (int ko = 0; ko < 32; ko += 8) {
            uint32_t af[2][4], bf[4][2];
            int qr = lane >> 2, qc = lane & 3;
            #pragma unroll
            for (int mi = 0; mi < 2; mi++) {
                int row = wm*32 + mi*16 + qr;
                af[mi][0] = As[row    ][ko + qc];
                af[mi][1] = As[row + 8][ko + qc];
                af[mi][2] = As[row    ][ko + 4 + qc];
                af[mi][3] = As[row + 8][ko + 4 + qc];
            }
            #pragma unroll
            for (int ni = 0; ni < 4; ni++) {
                int col = wn*32 + ni*8 + qr;
                bf[ni][0] = Bs[col][ko + qc];
                bf[ni][1] = Bs[col][ko + 4 + qc];
            }
            #pragma unroll
            for (int mi = 0; mi < 2; mi++)
                #pragma unroll
                for (int ni = 0; ni < 4; ni++)
                    mma_tf32(acc[mi][ni], af[mi], bf[ni]);
        }
        __syncthreads();
    }

    // epilogue
    int qr = lane >> 2, qc = lane & 3;
    #pragma unroll
    for (int mi = 0; mi < 2; mi++) {
        int row0 = bm + wm*32 + mi*16 + qr;
        #pragma unroll
        for (int ni = 0; ni < 4; ni++) {
            int col = bn + wn*32 + ni*8 + qc*2;
            float b0 = bias[col], b1 = bias[col + 1];
            float* cp0 = Cout + (size_t)row0*N + col;
            float* cp1 = Cout + (size_t)(row0 + 8)*N + col;
            float r00 = 0.f, r01 = 0.f, r10 = 0.f, r11 = 0.f;
            if (EPI == 1) {
                const float* rp0 = res + (size_t)row0*N + col;
                const float* rp1 = res + (size_t)(row0 + 8)*N + col;
                r00 = rp0[0]; r01 = rp0[1]; r10 = rp1[0]; r11 = rp1[1];
            }
            float2 o0, o1;
            o0.x = epi_apply(acc[mi][ni][0] + b0, r00, EPI);
            o0.y = epi_apply(acc[mi][ni][1] + b1, r01, EPI);
            o1.x = epi_apply(acc[mi][ni][2] + b0, r10, EPI);
            o1.y = epi_apply(acc[mi][ni][3] + b1, r11, EPI);
            *(float2*)cp0 = o0;
            *(float2*)cp1 = o1;
        }
    }
}

// ---------------- gather attention v2: block per (i, h), 128 threads ---------
// pass 1: thread-per-j dot products against transposed K, qe folded in smem
__global__ void attn2(const float* __restrict__ qkv, const float* __restrict__ Kt,
                      const int* __restrict__ bm,
                      const float* __restrict__ EKt, const float* __restrict__ EV,
                      const float* __restrict__ abe, float* __restrict__ y) {
    int i = blockIdx.x, h = blockIdx.y;
    int tid = threadIdx.x;                // 128
    int lane = tid & 31, wid = tid >> 5;

    __shared__ float qe_s[DD*EE];         // [d][e] = q[d]*EK[e][d]
    __shared__ float EV_s[EE*DD];         // [e][d]
    __shared__ float ab_s[EE];
    __shared__ float s_s[TT];
    __shared__ int   e_s[TT];
    __shared__ float psum[2][DD];
    __shared__ float rbuf[4];
    __shared__ float resv[2];

    const float* EKh = EKt + h*DD*EE;
    #pragma unroll
    for (int k = 0; k < 8; k++) {         // 1024 / 128
        int idx = tid + k*128;
        int d = idx >> 4;
        qe_s[idx] = qkv[(size_t)i*3*CC + h*DD + d] * EKh[idx];
        EV_s[idx] = EV[(size_t)(idx >> 6)*CC + h*DD + (idx & 63)];
    }
    if (tid < EE) ab_s[tid] = abe[tid*HH + h];
    __syncthreads();

    // pass 1: thread t handles j = t, t+128, t+256 (<= i)
    const float* KtH = Kt + (size_t)h*DD*TT;
    for (int j = tid; j <= i; j += 128) {
        int e = bm[i*TT + j];
        const float* kp = KtH + j;
        float s = 0.f;
        #pragma unroll 16
        for (int d = 0; d < DD; d++)
            s = fmaf(qe_s[d*EE + e], kp[(size_t)d*TT], s);
        s_s[j] = s * 0.125f + ab_s[e];
        e_s[j] = e;
    }
    __syncthreads();

    // block max over j in [0, i]
    float lm = -1e30f;
    for (int j = tid; j <= i; j += 128) lm = fmaxf(lm, s_s[j]);
    #pragma unroll
    for (int o = 16; o > 0; o >>= 1) lm = fmaxf(lm, __shfl_xor_sync(0xffffffffu, lm, o));
    if (lane == 0) rbuf[wid] = lm;
    __syncthreads();
    if (tid == 0) resv[0] = fmaxf(fmaxf(rbuf[0], rbuf[1]), fmaxf(rbuf[2], rbuf[3]));
    __syncthreads();
    float m = resv[0];

    // exp + sum
    float ls = 0.f;
    for (int j = tid; j <= i; j += 128) {
        float p = __expf(s_s[j] - m);
        s_s[j] = p;
        ls += p;
    }
    #pragma unroll
    for (int o = 16; o > 0; o >>= 1) ls += __shfl_xor_sync(0xffffffffu, ls, o);
    if (lane == 0) rbuf[wid] = ls;
    __syncthreads();
    if (tid == 0) resv[1] = 1.0f / (rbuf[0] + rbuf[1] + rbuf[2] + rbuf[3]);
    __syncthreads();
    float inv = resv[1];

    // pass 2: weighted V accumulate; threads split into 2 j-halves x 64 d
    int d = tid & 63, half = tid >> 6;
    float acc = 0.f;
    for (int j = half; j <= i; j += 2) {
        int e = e_s[j];
        acc = fmaf(s_s[j], qkv[(size_t)j*3*CC + 2*CC + h*DD + d] * EV_s[e*DD + d], acc);
    }
    psum[half][d] = acc;
    __syncthreads();
    if (tid < DD) y[(size_t)i*CC + h*DD + tid] = (psum[0][tid] + psum[1][tid]) * inv;
}

// ---------------- host launch ------------------------------------------------
extern "C" void kernel_launch(void* const* d_in, const int* in_sizes, int n_in,
                              void* d_out, int out_size) {
    const float* x        = (const float*)d_in[0];
    const int*   bmx      = (const int*)  d_in[1];
    const float* ln1_w    = (const float*)d_in[2];
    const float* ln1_b    = (const float*)d_in[3];
    const float* w_attn_w = (const float*)d_in[4];
    const float* w_attn_b = (const float*)d_in[5];
    const float* w_proj_w = (const float*)d_in[6];
    const float* w_proj_b = (const float*)d_in[7];
    const float* abe      = (const float*)d_in[8];
    const float* edge_emb = (const float*)d_in[9];
    const float* wek      = (const float*)d_in[10];
    const float* bek      = (const float*)d_in[11];
    const float* wev      = (const float*)d_in[12];
    const float* bev      = (const float*)d_in[13];
    const float* ln2_w    = (const float*)d_in[14];
    const float* ln2_b    = (const float*)d_in[15];
    const float* c_fc_w   = (const float*)d_in[16];
    const float* c_fc_b   = (const float*)d_in[17];
    const float* c_proj_w = (const float*)d_in[18];
    const float* c_proj_b = (const float*)d_in[19];
    float* out = (float*)d_out;

    float *pH, *pQKV, *pEK, *pEKt, *pEV, *pKt, *pY, *pX1, *pH2, *pFC;
    cudaGetSymbolAddress((void**)&pH,   g_h);
    cudaGetSymbolAddress((void**)&pQKV, g_qkv);
    cudaGetSymbolAddress((void**)&pEK,  g_EK);
    cudaGetSymbolAddress((void**)&pEKt, g_EKt);
    cudaGetSymbolAddress((void**)&pEV,  g_EV);
    cudaGetSymbolAddress((void**)&pKt,  g_Kt);
    cudaGetSymbolAddress((void**)&pY,   g_y);
    cudaGetSymbolAddress((void**)&pX1,  g_x1);
    cudaGetSymbolAddress((void**)&pH2,  g_h2);
    cudaGetSymbolAddress((void**)&pFC,  g_fc);

    // 1. edge tables
    edge_pre<<<EE, CC>>>(edge_emb, wek, bek, wev, bev, pEK, pEKt, pEV);
    // 2. LN1
    ln_kernel<<<TT, 256>>>(x, ln1_w, ln1_b, pH);
    // 3. QKV = LN1 @ w_attn^T + b   (384 x 1536 x 512)
    gemm_tc<0><<<dim3(3*CC/64, TT/64), 128>>>(pH, w_attn_w, w_attn_b, nullptr, pQKV, TT, 3*CC, CC);
    // 4. K transpose
    transpose_k<<<dim3(CC/32, TT/32), dim3(32, 8)>>>(pQKV, pKt);
    // 5. gather attention
    attn2<<<dim3(TT, HH), 128>>>(pQKV, pKt, bmx, pEKt, pEV, abe, pY);
    // 6. x1 = x + y @ w_proj^T + b  (384 x 512 x 512)
    gemm_tc<1><<<dim3(CC/64, TT/64), 128>>>(pY, w_proj_w, w_proj_b, x, pX1, TT, CC, CC);
    // 7. LN2
    ln_kernel<<<TT, 256>>>(pX1, ln2_w, ln2_b, pH2);
    // 8. fc = gelu(h2 @ c_fc^T + b) (384 x 2048 x 512)
    gemm_tc<2><<<dim3(4*CC/64, TT/64), 128>>>(pH2, c_fc_w, c_fc_b, nullptr, pFC, TT, 4*CC, CC);
    // 9. out = x1 + fc @ c_proj^T + b (384 x 512 x 2048)
    gemm_tc<1><<<dim3(CC/64, TT/64), 128>>>(pFC, c_proj_w, c_proj_b, pX1, out, TT, CC, 4*CC);
}